// round 2
// baseline (speedup 1.0000x reference)
#include <cuda_runtime.h>

#define NV 8192
#define DIN 256
#define FD 128
#define MAXE 640
#define NF (NV*FD)
#define FULLMASK 0xFFFFFFFFu

// ---------------- device scratch (no runtime allocation allowed) ----------------
__device__ float g_proj[2 * NF];               // [h][n][f]
__device__ float g_res[NF];                    // x @ W_res^T
__device__ float g_vals[NF];                   // head-mean attention output
__device__ unsigned short g_cols[NV * MAXE];   // CSR col indices per row
__device__ int   g_rowcnt[NV];
__device__ float g_ssrc[2 * NV], g_ea[2 * NV], g_ea2[2 * NV];
__device__ float g_stgt[2 * NV], g_eb[2 * NV], g_eb2[2 * NV];
__device__ float g_PQ[4 * NV];                 // [h0P, h0Q, h1P, h1Q]
__device__ float g_czp[2 * NV], g_czn[2 * NV]; // 0.5*eb/Z, 0.5*eb2/Z
__device__ double g_sum[2];                    // sum, sumsq

// ---------------- K0: zero accumulators (every graph replay) ----------------
__global__ void k0_zero() {
    int i = blockIdx.x * 256 + threadIdx.x;
    if (i < 4 * NV) g_PQ[i] = 0.0f;
    if (i < 2) g_sum[i] = 0.0;
}

// ---------------- K1: fused SGEMM  C = x @ [W0 | W1 | Wres^T] ----------------
// BM=128, BN=128, BK=16, 256 threads, 8x8 microtile. grid (64, 3): y=0/1 heads, y=2 residual.
__global__ __launch_bounds__(256) void k1_gemm(const float* __restrict__ x,
                                               const float* __restrict__ W,
                                               const float* __restrict__ Wres) {
    __shared__ float As[16][132];   // 132*4=528 bytes/row, 16B-aligned rows
    __shared__ float Bs[16][128];
    const int m0 = blockIdx.x * 128;
    const int which = blockIdx.y;
    const int tid = threadIdx.x;
    const int tx = tid & 15, ty = tid >> 4;

    float acc[8][8];
#pragma unroll
    for (int i = 0; i < 8; i++)
#pragma unroll
        for (int j = 0; j < 8; j++) acc[i][j] = 0.0f;

    const int mA = tid >> 1;           // 0..127
    const int kA = (tid & 1) * 8;      // 0 or 8

    for (int k0 = 0; k0 < DIN; k0 += 16) {
        // A tile: x[m0+mA][k0+kA .. +8)
        {
            const float* src = x + (size_t)(m0 + mA) * DIN + k0 + kA;
            float4 v0 = *(const float4*)(src);
            float4 v1 = *(const float4*)(src + 4);
            As[kA + 0][mA] = v0.x; As[kA + 1][mA] = v0.y;
            As[kA + 2][mA] = v0.z; As[kA + 3][mA] = v0.w;
            As[kA + 4][mA] = v1.x; As[kA + 5][mA] = v1.y;
            As[kA + 6][mA] = v1.z; As[kA + 7][mA] = v1.w;
        }
        // B tile
        if (which < 2) {
            int k = tid >> 4, f = (tid & 15) * 8;
            const float* src = W + ((size_t)which * DIN + (k0 + k)) * FD + f;
            float4 v0 = *(const float4*)(src);
            float4 v1 = *(const float4*)(src + 4);
            *(float4*)&Bs[k][f] = v0;
            *(float4*)&Bs[k][f + 4] = v1;
        } else {
            int f = tid >> 1;   // 0..127
            const float* src = Wres + (size_t)f * DIN + k0 + kA;
            float4 v0 = *(const float4*)(src);
            float4 v1 = *(const float4*)(src + 4);
            Bs[kA + 0][f] = v0.x; Bs[kA + 1][f] = v0.y;
            Bs[kA + 2][f] = v0.z; Bs[kA + 3][f] = v0.w;
            Bs[kA + 4][f] = v1.x; Bs[kA + 5][f] = v1.y;
            Bs[kA + 6][f] = v1.z; Bs[kA + 7][f] = v1.w;
        }
        __syncthreads();

#pragma unroll
        for (int kk = 0; kk < 16; kk++) {
            float4 ra0 = *(const float4*)&As[kk][ty * 8];
            float4 ra1 = *(const float4*)&As[kk][ty * 8 + 4];
            float4 rb0 = *(const float4*)&Bs[kk][tx * 8];
            float4 rb1 = *(const float4*)&Bs[kk][tx * 8 + 4];
            float ra[8] = {ra0.x, ra0.y, ra0.z, ra0.w, ra1.x, ra1.y, ra1.z, ra1.w};
            float rb[8] = {rb0.x, rb0.y, rb0.z, rb0.w, rb1.x, rb1.y, rb1.z, rb1.w};
#pragma unroll
            for (int i = 0; i < 8; i++)
#pragma unroll
                for (int j = 0; j < 8; j++) acc[i][j] += ra[i] * rb[j];
        }
        __syncthreads();
    }

    float* dst = (which < 2) ? &g_proj[(size_t)which * NF] : g_res;
#pragma unroll
    for (int i = 0; i < 8; i++) {
        int row = m0 + ty * 8 + i;
        float4 w0 = make_float4(acc[i][0], acc[i][1], acc[i][2], acc[i][3]);
        float4 w1 = make_float4(acc[i][4], acc[i][5], acc[i][6], acc[i][7]);
        *(float4*)&dst[(size_t)row * FD + tx * 8]     = w0;
        *(float4*)&dst[(size_t)row * FD + tx * 8 + 4] = w1;
    }
}

// ---------------- K2: per-node dots + 8 exps ----------------
__global__ __launch_bounds__(256) void k2_scal(const float* __restrict__ asrc,
                                               const float* __restrict__ atgt) {
    int w = blockIdx.x * 8 + (threadIdx.x >> 5);
    int lane = threadIdx.x & 31;
    if (w >= 2 * NV) return;
    int h = w >> 13;
    const float* pr = &g_proj[(size_t)w * FD];
    const float* as = asrc + h * FD;
    const float* at = atgt + h * FD;
    float s1 = 0.0f, s2 = 0.0f;
#pragma unroll
    for (int j = 0; j < 4; j++) {
        float p = pr[lane + 32 * j];
        s1 += p * as[lane + 32 * j];
        s2 += p * at[lane + 32 * j];
    }
#pragma unroll
    for (int o = 16; o; o >>= 1) {
        s1 += __shfl_xor_sync(FULLMASK, s1, o);
        s2 += __shfl_xor_sync(FULLMASK, s2, o);
    }
    if (lane == 0) {
        g_ssrc[w] = s1; g_ea[w] = expf(s1); g_ea2[w] = expf(0.2f * s1);
        g_stgt[w] = s2; g_eb[w] = expf(s2); g_eb2[w] = expf(0.2f * s2);
    }
}

// ---------------- K3: single mask pass: copy-out + CSR build ----------------
__global__ __launch_bounds__(256) void k3_mask(const float4* __restrict__ conn,
                                               float4* __restrict__ outmask) {
    int m = blockIdx.x * 8 + (threadIdx.x >> 5);
    int lane = threadIdx.x & 31;
    const float4* src = conn + (size_t)m * (NV / 4);
    float4* dst = outmask + (size_t)m * (NV / 4);
    unsigned short* cols = &g_cols[(size_t)m * MAXE];
    int cnt = 0;
#pragma unroll 2
    for (int it = 0; it < NV / 128; it++) {
        int q = it * 32 + lane;
        float4 v = src[q];
        dst[q] = v;
        unsigned b0 = __ballot_sync(FULLMASK, v.x == 0.0f);
        unsigned b1 = __ballot_sync(FULLMASK, v.y == 0.0f);
        unsigned b2 = __ballot_sync(FULLMASK, v.z == 0.0f);
        unsigned b3 = __ballot_sync(FULLMASK, v.w == 0.0f);
        unsigned lt = (1u << lane) - 1u;
        int o = cnt + __popc(b0 & lt) + __popc(b1 & lt) + __popc(b2 & lt) + __popc(b3 & lt);
        int col0 = it * 128 + lane * 4;
        if (v.x == 0.0f) { if (o < MAXE) cols[o] = (unsigned short)(col0);     o++; }
        if (v.y == 0.0f) { if (o < MAXE) cols[o] = (unsigned short)(col0 + 1); o++; }
        if (v.z == 0.0f) { if (o < MAXE) cols[o] = (unsigned short)(col0 + 2); o++; }
        if (v.w == 0.0f) { if (o < MAXE) cols[o] = (unsigned short)(col0 + 3); o++; }
        cnt += __popc(b0) + __popc(b1) + __popc(b2) + __popc(b3);
    }
    if (lane == 0) g_rowcnt[m] = min(cnt, MAXE);
}

// ---------------- K4: per-edge sign-split column sums P/Q ----------------
__global__ __launch_bounds__(256) void k4_z() {
    int m = blockIdx.x * 8 + (threadIdx.x >> 5);
    int lane = threadIdx.x & 31;
    int cnt = g_rowcnt[m];
    float ss0 = g_ssrc[m],      ea0 = g_ea[m],      ea20 = g_ea2[m];
    float ss1 = g_ssrc[NV + m], ea1 = g_ea[NV + m], ea21 = g_ea2[NV + m];
    const unsigned short* cols = &g_cols[(size_t)m * MAXE];
    for (int e = lane; e < cnt; e += 32) {
        int n = cols[e];
        float st0 = g_stgt[n], st1 = g_stgt[NV + n];
        if (ss0 + st0 > 0.0f) atomicAdd(&g_PQ[n], ea0);
        else                  atomicAdd(&g_PQ[NV + n], ea20);
        if (ss1 + st1 > 0.0f) atomicAdd(&g_PQ[2 * NV + n], ea1);
        else                  atomicAdd(&g_PQ[3 * NV + n], ea21);
    }
}

// ---------------- K5: fold Z into per-column coefficients (incl. 0.5 head-mean) ----------------
__global__ void k5_cz() {
    int n = blockIdx.x * 256 + threadIdx.x;
    if (n >= NV) return;
    float Z0 = g_eb[n] * g_PQ[n] + g_eb2[n] * g_PQ[NV + n];
    g_czp[n] = 0.5f * g_eb[n]  / Z0;
    g_czn[n] = 0.5f * g_eb2[n] / Z0;
    float Z1 = g_eb[NV + n] * g_PQ[2 * NV + n] + g_eb2[NV + n] * g_PQ[3 * NV + n];
    g_czp[NV + n] = 0.5f * g_eb[NV + n]  / Z1;
    g_czn[NV + n] = 0.5f * g_eb2[NV + n] / Z1;
}

// ---------------- K6: sparse vals (head-summed) — warp per row, L2 gather ----------------
__global__ __launch_bounds__(256) void k6_spmm() {
    int m = blockIdx.x * 8 + (threadIdx.x >> 5);
    int lane = threadIdx.x & 31;
    int cnt = g_rowcnt[m];
    float ss0 = g_ssrc[m],      ea0 = g_ea[m],      ea20 = g_ea2[m];
    float ss1 = g_ssrc[NV + m], ea1 = g_ea[NV + m], ea21 = g_ea2[NV + m];
    const unsigned short* cols = &g_cols[(size_t)m * MAXE];
    float4 acc = make_float4(0.0f, 0.0f, 0.0f, 0.0f);
#pragma unroll 2
    for (int e = 0; e < cnt; e++) {
        int n = cols[e];
        float st0 = g_stgt[n], st1 = g_stgt[NV + n];
        float c0 = (ss0 + st0 > 0.0f) ? ea0 * g_czp[n]      : ea20 * g_czn[n];
        float c1 = (ss1 + st1 > 0.0f) ? ea1 * g_czp[NV + n] : ea21 * g_czn[NV + n];
        float4 a = *(const float4*)&g_proj[(size_t)n * FD + lane * 4];
        float4 b = *(const float4*)&g_proj[(size_t)(NV + n) * FD + lane * 4];
        acc.x += c0 * a.x; acc.y += c0 * a.y; acc.z += c0 * a.z; acc.w += c0 * a.w;
        acc.x += c1 * b.x; acc.y += c1 * b.y; acc.z += c1 * b.z; acc.w += c1 * b.w;
    }
    *(float4*)&g_vals[(size_t)m * FD + lane * 4] = acc;
}

// ---------------- K7: instance-norm stats (double accumulation) ----------------
__global__ __launch_bounds__(256) void k7_stats() {
    __shared__ double sdat[2][8];
    double s = 0.0, s2 = 0.0;
    for (int i = blockIdx.x * 256 + threadIdx.x; i < NF; i += gridDim.x * 256) {
        double v = (double)g_vals[i];
        s += v; s2 += v * v;
    }
#pragma unroll
    for (int o = 16; o; o >>= 1) {
        s  += __shfl_xor_sync(FULLMASK, s, o);
        s2 += __shfl_xor_sync(FULLMASK, s2, o);
    }
    int wid = threadIdx.x >> 5, lane = threadIdx.x & 31;
    if (lane == 0) { sdat[0][wid] = s; sdat[1][wid] = s2; }
    __syncthreads();
    if (threadIdx.x == 0) {
        double t = 0.0, t2 = 0.0;
        for (int i = 0; i < 8; i++) { t += sdat[0][i]; t2 += sdat[1][i]; }
        atomicAdd(&g_sum[0], t);
        atomicAdd(&g_sum[1], t2);
    }
}

// ---------------- K8: normalize + residual + ELU ----------------
__global__ void k8_final(float* __restrict__ out) {
    int i = blockIdx.x * 256 + threadIdx.x;
    if (i >= NF) return;
    double mu_d = g_sum[0] / (double)NF;
    double var_d = g_sum[1] / (double)NF - mu_d * mu_d;
    float mu = (float)mu_d;
    float inv = rsqrtf((float)var_d + 1e-5f);
    float v = (g_vals[i] - mu) * inv + g_res[i];
    out[i] = v > 0.0f ? v : expm1f(v);
}

// ---------------- launch ----------------
extern "C" void kernel_launch(void* const* d_in, const int* in_sizes, int n_in,
                              void* d_out, int out_size) {
    const float* x    = (const float*)d_in[0];
    const float* conn = (const float*)d_in[1];
    const float* W    = (const float*)d_in[2];
    const float* asrc = (const float*)d_in[3];
    const float* atgt = (const float*)d_in[4];
    const float* wres = (const float*)d_in[5];
    float* out = (float*)d_out;
    float* outmask = out + NF;      // tuple: (out [N,F], conn_mask [N,N])

    k0_zero<<<128, 256>>>();
    k1_gemm<<<dim3(64, 3), 256>>>(x, W, wres);
    k2_scal<<<2048, 256>>>(asrc, atgt);
    k3_mask<<<1024, 256>>>((const float4*)conn, (float4*)outmask);
    k4_z<<<1024, 256>>>();
    k5_cz<<<32, 256>>>();
    k6_spmm<<<1024, 256>>>();
    k7_stats<<<512, 256>>>();
    k8_final<<<NF / 256, 256>>>(out);
}